// round 7
// baseline (speedup 1.0000x reference)
#include <cuda_runtime.h>
#include <cuda_fp16.h>
#include <math.h>
#include <stdint.h>

// Problem constants (fixed shapes: B=4096, D=256, T=0.5)
#define NB     4096
#define D      256
#define N2     8192
#define BM     128
#define BN     128
#define BK     32
#define NKC    (D / BK)      // 8 k-chunks
#define NCT    (N2 / BN)     // 64 col tiles
#define NRT    (N2 / BM)     // 64 row tiles
#define NTRI   (NRT * (NRT + 1) / 2)   // 2080 upper-tri tiles
#define NPERS  304           // persistent CTAs (2/SM)
#define PITCH  80            // smem row pitch bytes (64B data + 16B pad)
#define STAGE_BYTES (2 * BM * PITCH)   // A + B tile = 20480
#define NSTAGE 4
#define REDR_OFF (NSTAGE * STAGE_BYTES)          // 81920: red_row[128][4]
#define REDC_OFF (REDR_OFF + BM * 4 * 4)         // red_col[128][2]
#define SMEM_BYTES (REDC_OFF + BM * 2 * 4)
#define FBLK   64            // kfinal1 blocks (128 rows each)

// Scratch (static device globals; no allocation allowed)
__device__ __half g_zh[N2 * D];        // normalized rows, fp16
__device__ float g_partial[N2 * NCT];  // per-row exp-sum partial per slot
__device__ float g_pos[N2];            // sim[k, k +- NB]
__device__ float g_blocksum[FBLK];     // per-block loss partial
__device__ int   g_ctr;                // kfinal completion counter

// ---------------------------------------------------------------------------
__device__ __forceinline__ uint32_t smem_u32(const void* p) {
    uint32_t a;
    asm("{ .reg .u64 t; cvta.to.shared.u64 t, %1; cvt.u32.u64 %0, t; }"
        : "=r"(a) : "l"(p));
    return a;
}
__device__ __forceinline__ void cp_async16(uint32_t smem, const void* g) {
    asm volatile("cp.async.cg.shared.global [%0], [%1], 16;" :: "r"(smem), "l"(g));
}
#define CP_COMMIT() asm volatile("cp.async.commit_group;" ::: "memory")
#define CP_WAIT(n)  asm volatile("cp.async.wait_group %0;" :: "n"(n) : "memory")

__device__ __forceinline__ void ldsm4(uint32_t* r, uint32_t addr) {
    asm volatile("ldmatrix.sync.aligned.m8n8.x4.shared.b16 {%0,%1,%2,%3}, [%4];"
        : "=r"(r[0]), "=r"(r[1]), "=r"(r[2]), "=r"(r[3]) : "r"(addr));
}
__device__ __forceinline__ void mma16816(float* c, const uint32_t* a, const uint32_t* b) {
    asm volatile("mma.sync.aligned.m16n8k16.row.col.f32.f16.f16.f32 "
        "{%0,%1,%2,%3}, {%4,%5,%6,%7}, {%8,%9}, {%0,%1,%2,%3};"
        : "+f"(c[0]), "+f"(c[1]), "+f"(c[2]), "+f"(c[3])
        : "r"(a[0]), "r"(a[1]), "r"(a[2]), "r"(a[3]), "r"(b[0]), "r"(b[1]));
}

__device__ __forceinline__ void tri_decode(int t, int& it, int& jt) {
    int rem = t, i = 0;
    while (rem >= NRT - i) { rem -= NRT - i; i++; }
    it = i; jt = i + rem;
}

// ---------------------------------------------------------------------------
// Kernel 1: L2-normalize rows (fp32 math) into fp16 g_zh. 2 rows per warp.
// ---------------------------------------------------------------------------
__global__ __launch_bounds__(256) void knorm(const float* __restrict__ xi,
                                             const float* __restrict__ xj) {
    if (blockIdx.x == 0 && threadIdx.x == 0) g_ctr = 0;   // reset kfinal counter
    const int warp = threadIdx.x >> 5;
    const int lane = threadIdx.x & 31;
    const int row0 = blockIdx.x * 16 + warp * 2;

    float4 v0[2], v1[2];
    float ss[2];
#pragma unroll
    for (int r = 0; r < 2; r++) {
        const int row = row0 + r;
        const float* src = (row < NB) ? (xi + (size_t)row * D)
                                      : (xj + (size_t)(row - NB) * D);
        v0[r] = ((const float4*)src)[lane];
        v1[r] = ((const float4*)src)[lane + 32];
        ss[r] = v0[r].x*v0[r].x + v0[r].y*v0[r].y + v0[r].z*v0[r].z + v0[r].w*v0[r].w
              + v1[r].x*v1[r].x + v1[r].y*v1[r].y + v1[r].z*v1[r].z + v1[r].w*v1[r].w;
    }
#pragma unroll
    for (int off = 16; off > 0; off >>= 1) {
        ss[0] += __shfl_xor_sync(0xffffffffu, ss[0], off);
        ss[1] += __shfl_xor_sync(0xffffffffu, ss[1], off);
    }
#pragma unroll
    for (int r = 0; r < 2; r++) {
        const float sc = 1.0f / fmaxf(sqrtf(ss[r]), 1e-12f);
        __half2* dst = (__half2*)(g_zh + (size_t)(row0 + r) * D);
        dst[lane * 2 + 0]  = __floats2half2_rn(v0[r].x * sc, v0[r].y * sc);
        dst[lane * 2 + 1]  = __floats2half2_rn(v0[r].z * sc, v0[r].w * sc);
        dst[64 + lane * 2] = __floats2half2_rn(v1[r].x * sc, v1[r].y * sc);
        dst[65 + lane * 2] = __floats2half2_rn(v1[r].z * sc, v1[r].w * sc);
    }
}

// ---------------------------------------------------------------------------
// Stage loader: A(128x32) + B(128x32) fp16 tiles via cp.async.
// ---------------------------------------------------------------------------
__device__ __forceinline__ void load_stage(uint32_t sbase, int rb, int cb,
                                           int k0, int tid) {
    const uint32_t aB = sbase, bB = sbase + BM * PITCH;
#pragma unroll
    for (int i = 0; i < 2; i++) {
        int t = tid + i * 256;
        int row = t >> 2, seg = t & 3;
        uint32_t so = (uint32_t)(row * PITCH + seg * 16);
        cp_async16(aB + so, g_zh + (size_t)(rb + row) * D + k0 + seg * 8);
        cp_async16(bB + so, g_zh + (size_t)(cb + row) * D + k0 + seg * 8);
    }
}

// ---------------------------------------------------------------------------
// Kernel 2: persistent fp16 HMMA sim-GEMM, upper-triangular tiles (symmetry).
// Cross-tile cp.async ring: pipeline never drains; next tile's chunks load
// during this tile's epilogue. Empty commit groups keep wait-count invariant.
// ---------------------------------------------------------------------------
__global__ __launch_bounds__(256, 2) void kmain_hmma() {
    extern __shared__ char smem[];
    const uint32_t sb = smem_u32(smem);
    float* red_row = (float*)(smem + REDR_OFF);   // [128][4]
    float* red_col = (float*)(smem + REDC_OFF);   // [128][2]

    const int tid = threadIdx.x;
    const int wid = tid >> 5, lid = tid & 31;
    const int wm = wid >> 2;                  // 0..1  (rows wm*64)
    const int wn = wid & 3;                   // 0..3  (cols wn*32)

    // Prefetch cursor over the global (tile, chunk) stream.
    int pf_t = blockIdx.x, pf_k = 0;
    int pf_rb = 0, pf_cb = 0;
    if (pf_t < NTRI) {
        int pi, pj; tri_decode(pf_t, pi, pj);
        pf_rb = pi * BM; pf_cb = pj * BN;
    }
    int pstage = 0;
#pragma unroll
    for (int p = 0; p < 3; p++) {
        if (pf_t < NTRI)
            load_stage(sb + pstage * STAGE_BYTES, pf_rb, pf_cb, pf_k * BK, tid);
        CP_COMMIT();
        pstage = (pstage + 1) & 3;
        if (++pf_k == NKC) {
            pf_k = 0; pf_t += NPERS;
            if (pf_t < NTRI) {
                int pi, pj; tri_decode(pf_t, pi, pj);
                pf_rb = pi * BM; pf_cb = pj * BN;
            }
        }
    }

    const int arow  = (lid & 7) + ((lid >> 3) & 1) * 8;
    const int akoff = (lid >> 4) * 16;
    // B ldsm4 addressing: matrix m = lid>>3; j-sub = m>>1, k-half = m&1
    const int bjrow = ((lid >> 4) & 1) * 8 + (lid & 7);
    const int bkoff = ((lid >> 3) & 1) * 16;

    int cstage = 0;
    for (int t = blockIdx.x; t < NTRI; t += NPERS) {
        int it, jt; tri_decode(t, it, jt);
        const bool offd = (jt > it);
        const bool haspos = (jt == it + NB / BM);
        const int rb = it * BM;
        const int cb = jt * BN;

        float acc[4][4][4];
#pragma unroll
        for (int i = 0; i < 4; i++)
#pragma unroll
            for (int j = 0; j < 4; j++)
#pragma unroll
                for (int e = 0; e < 4; e++) acc[i][j][e] = 0.0f;

#pragma unroll
        for (int k = 0; k < NKC; k++) {
            CP_WAIT(2);
            __syncthreads();
            if (pf_t < NTRI)
                load_stage(sb + pstage * STAGE_BYTES, pf_rb, pf_cb, pf_k * BK, tid);
            CP_COMMIT();
            pstage = (pstage + 1) & 3;
            if (++pf_k == NKC) {
                pf_k = 0; pf_t += NPERS;
                if (pf_t < NTRI) {
                    int pi, pj; tri_decode(pf_t, pi, pj);
                    pf_rb = pi * BM; pf_cb = pj * BN;
                }
            }

            const uint32_t aB = sb + cstage * STAGE_BYTES;
            const uint32_t bB = aB + BM * PITCH;
            cstage = (cstage + 1) & 3;
#pragma unroll
            for (int kf = 0; kf < 2; kf++) {
                uint32_t af[4][4], bf[4][2];
#pragma unroll
                for (int i = 0; i < 4; i++)
                    ldsm4(af[i], aB + (uint32_t)((wm * 64 + i * 16 + arow) * PITCH
                                                 + kf * 32 + akoff));
#pragma unroll
                for (int q = 0; q < 2; q++) {
                    uint32_t br[4];
                    ldsm4(br, bB + (uint32_t)((wn * 32 + q * 16 + bjrow) * PITCH
                                              + kf * 32 + bkoff));
                    bf[q * 2 + 0][0] = br[0]; bf[q * 2 + 0][1] = br[1];
                    bf[q * 2 + 1][0] = br[2]; bf[q * 2 + 1][1] = br[3];
                }
#pragma unroll
                for (int i = 0; i < 4; i++)
#pragma unroll
                    for (int j = 0; j < 4; j++)
                        mma16816(acc[i][j], af[i], bf[j]);
            }
        }

        // Fragment coords: row = wm*64 + i*16 + (lid>>2) + (e>=2)*8
        //                  col = wn*32 + j*8  + (lid&3)*2 + (e&1)
        const int r0 = lid >> 2;
        const int c0 = (lid & 3) * 2;

        // Pass 0: exp in place (+ pos capture, + self-diag mask on diag tiles)
#pragma unroll
        for (int i = 0; i < 4; i++)
#pragma unroll
            for (int j = 0; j < 4; j++)
#pragma unroll
                for (int e = 0; e < 4; e++) {
                    const float v = acc[i][j][e];
                    float ev = __expf(v * 2.0f);
                    if (haspos) {
                        const int lm = wm * 64 + i * 16 + r0 + (e >> 1) * 8;
                        const int ln = wn * 32 + j * 8 + c0 + (e & 1);
                        if (ln == lm) { g_pos[rb + lm] = v; g_pos[cb + ln] = v; }
                    }
                    if (!offd) {
                        const int lm = wm * 64 + i * 16 + r0 + (e >> 1) * 8;
                        const int ln = wn * 32 + j * 8 + c0 + (e & 1);
                        if (ln == lm) ev = 0.0f;     // exclude self-similarity
                    }
                    acc[i][j][e] = ev;
                }

        // Pass 1: row sums -> red_row
        {
            float rsum[4][2];
#pragma unroll
            for (int i = 0; i < 4; i++) { rsum[i][0] = 0.0f; rsum[i][1] = 0.0f; }
#pragma unroll
            for (int i = 0; i < 4; i++)
#pragma unroll
                for (int j = 0; j < 4; j++) {
                    rsum[i][0] += acc[i][j][0] + acc[i][j][1];
                    rsum[i][1] += acc[i][j][2] + acc[i][j][3];
                }
#pragma unroll
            for (int i = 0; i < 4; i++)
#pragma unroll
                for (int h = 0; h < 2; h++) {
#pragma unroll
                    for (int off = 1; off <= 2; off <<= 1)
                        rsum[i][h] += __shfl_xor_sync(0xffffffffu, rsum[i][h], off);
                }
            if ((lid & 3) == 0) {
#pragma unroll
                for (int i = 0; i < 4; i++)
#pragma unroll
                    for (int h = 0; h < 2; h++)
                        red_row[(wm * 64 + i * 16 + r0 + h * 8) * 4 + wn] = rsum[i][h];
            }
        }

        // Pass 2 (off-diag only): col sums -> red_col
        if (offd) {
            float csum[4][2];
#pragma unroll
            for (int j = 0; j < 4; j++) { csum[j][0] = 0.0f; csum[j][1] = 0.0f; }
#pragma unroll
            for (int i = 0; i < 4; i++)
#pragma unroll
                for (int j = 0; j < 4; j++) {
                    csum[j][0] += acc[i][j][0] + acc[i][j][2];
                    csum[j][1] += acc[i][j][1] + acc[i][j][3];
                }
#pragma unroll
            for (int j = 0; j < 4; j++)
#pragma unroll
                for (int ec = 0; ec < 2; ec++) {
#pragma unroll
                    for (int off = 4; off <= 16; off <<= 1)
                        csum[j][ec] += __shfl_xor_sync(0xffffffffu, csum[j][ec], off);
                }
            if (lid < 4) {
#pragma unroll
                for (int j = 0; j < 4; j++)
#pragma unroll
                    for (int ec = 0; ec < 2; ec++)
                        red_col[(wn * 32 + j * 8 + lid * 2 + ec) * 2 + wm] = csum[j][ec];
            }
        }
        __syncthreads();
        if (tid < BM) {
            g_partial[(size_t)(rb + tid) * NCT + jt] =
                red_row[tid * 4] + red_row[tid * 4 + 1]
              + red_row[tid * 4 + 2] + red_row[tid * 4 + 3];
            if (offd)
                g_partial[(size_t)(cb + tid) * NCT + it] =
                    red_col[tid * 2] + red_col[tid * 2 + 1];
        }
        __syncthreads();   // red_* reuse protection for next tile
    }
}

// ---------------------------------------------------------------------------
// Kernel 3: coalesced per-row loss; last block combines deterministically.
// 64 blocks x 256 threads; block b covers rows [b*128, b*128+128).
// ---------------------------------------------------------------------------
__global__ __launch_bounds__(256) void kfinal1(float* __restrict__ out) {
    __shared__ float red[8];
    __shared__ int last;
    const int warp = threadIdx.x >> 5;
    const int lane = threadIdx.x & 31;
    float acc = 0.0f;
#pragma unroll
    for (int rr = 0; rr < 16; rr++) {
        const int row = blockIdx.x * 128 + warp * 16 + rr;
        const float* p = g_partial + (size_t)row * NCT;
        float s = p[lane] + p[lane + 32];
#pragma unroll
        for (int off = 16; off > 0; off >>= 1)
            s += __shfl_xor_sync(0xffffffffu, s, off);
        if (lane == 0) acc += -g_pos[row] * 2.0f + logf(s);
    }
    if (lane == 0) red[warp] = acc;
    __syncthreads();
    if (threadIdx.x == 0) {
        float t = 0.0f;
#pragma unroll
        for (int w = 0; w < 8; w++) t += red[w];
        g_blocksum[blockIdx.x] = t;
        __threadfence();
        last = (atomicAdd(&g_ctr, 1) == FBLK - 1);
    }
    __syncthreads();
    if (last && threadIdx.x == 0) {
        float t = 0.0f;
#pragma unroll
        for (int b = 0; b < FBLK; b++) t += g_blocksum[b];  // fixed order
        out[0] = t / (float)N2;
    }
}

// ---------------------------------------------------------------------------
extern "C" void kernel_launch(void* const* d_in, const int* in_sizes, int n_in,
                              void* d_out, int out_size) {
    const float* xi = (const float*)d_in[0];
    const float* xj = (const float*)d_in[1];
    float* out = (float*)d_out;
    (void)in_sizes; (void)n_in; (void)out_size;

    cudaFuncSetAttribute(kmain_hmma,
                         cudaFuncAttributeMaxDynamicSharedMemorySize, SMEM_BYTES);

    knorm<<<N2 / 16, 256>>>(xi, xj);
    kmain_hmma<<<NPERS, 256, SMEM_BYTES>>>();
    kfinal1<<<FBLK, 256>>>(out);
}

// round 8
// speedup vs baseline: 1.0756x; 1.0756x over previous
#include <cuda_runtime.h>
#include <cuda_fp16.h>
#include <math.h>
#include <stdint.h>

// Problem constants (fixed shapes: B=4096, D=256, T=0.5)
#define NB     4096
#define D      256
#define N2     8192
#define BM     128
#define BN     128
#define BK     32
#define NKC    (D / BK)      // 8 k-chunks
#define NCT    (N2 / BN)     // 64 col tiles
#define NRT    (N2 / BM)     // 64 row tiles
#define NTRI   (NRT * (NRT + 1) / 2)   // 2080 upper-tri tiles
#define PITCH  80            // smem row pitch bytes (64B data + 16B pad)
#define STAGE_BYTES (2 * BM * PITCH)   // A + B tile = 20480
#define NSTAGE 4
#define REDR_OFF (NSTAGE * STAGE_BYTES)          // 81920: red_row[128][4]
#define REDC_OFF (REDR_OFF + BM * 4 * 4)         // red_col[128][2]
#define SMEM_BYTES (REDC_OFF + BM * 2 * 4)
#define FBLK   64            // kfinal blocks (128 rows each)

// Scratch (static device globals; no allocation allowed)
__device__ __half g_zh[N2 * D];        // normalized rows, fp16
__device__ float g_partial[N2 * NCT];  // per-row exp-sum partial per slot
__device__ float g_pos[N2];            // sim[k, k +- NB]
__device__ float g_blocksum[FBLK];     // per-block loss partial
__device__ int   g_ctr;                // kfinal completion counter

// ---------------------------------------------------------------------------
__device__ __forceinline__ uint32_t smem_u32(const void* p) {
    uint32_t a;
    asm("{ .reg .u64 t; cvta.to.shared.u64 t, %1; cvt.u32.u64 %0, t; }"
        : "=r"(a) : "l"(p));
    return a;
}
__device__ __forceinline__ void cp_async16(uint32_t smem, const void* g) {
    asm volatile("cp.async.cg.shared.global [%0], [%1], 16;" :: "r"(smem), "l"(g));
}
#define CP_COMMIT() asm volatile("cp.async.commit_group;" ::: "memory")
#define CP_WAIT(n)  asm volatile("cp.async.wait_group %0;" :: "n"(n) : "memory")

__device__ __forceinline__ void ldsm4(uint32_t* r, uint32_t addr) {
    asm volatile("ldmatrix.sync.aligned.m8n8.x4.shared.b16 {%0,%1,%2,%3}, [%4];"
        : "=r"(r[0]), "=r"(r[1]), "=r"(r[2]), "=r"(r[3]) : "r"(addr));
}
__device__ __forceinline__ void mma16816(float* c, const uint32_t* a, const uint32_t* b) {
    asm volatile("mma.sync.aligned.m16n8k16.row.col.f32.f16.f16.f32 "
        "{%0,%1,%2,%3}, {%4,%5,%6,%7}, {%8,%9}, {%0,%1,%2,%3};"
        : "+f"(c[0]), "+f"(c[1]), "+f"(c[2]), "+f"(c[3])
        : "r"(a[0]), "r"(a[1]), "r"(a[2]), "r"(a[3]), "r"(b[0]), "r"(b[1]));
}

// ---------------------------------------------------------------------------
// Kernel 1: L2-normalize rows of x_i / x_j (fp32 math) into fp16 g_zh.
// ---------------------------------------------------------------------------
__global__ __launch_bounds__(256) void knorm(const float* __restrict__ xi,
                                             const float* __restrict__ xj) {
    if (blockIdx.x == 0 && threadIdx.x == 0) g_ctr = 0;   // reset kfinal counter
    int warp = threadIdx.x >> 5;
    int lane = threadIdx.x & 31;
    int row  = blockIdx.x * 8 + warp;
    const float* src = (row < NB) ? (xi + (size_t)row * D)
                                  : (xj + (size_t)(row - NB) * D);
    float4 v0 = ((const float4*)src)[lane];
    float4 v1 = ((const float4*)src)[lane + 32];
    float ss = v0.x*v0.x + v0.y*v0.y + v0.z*v0.z + v0.w*v0.w
             + v1.x*v1.x + v1.y*v1.y + v1.z*v1.z + v1.w*v1.w;
#pragma unroll
    for (int off = 16; off > 0; off >>= 1)
        ss += __shfl_xor_sync(0xffffffffu, ss, off);
    float sc = 1.0f / fmaxf(sqrtf(ss), 1e-12f);
    __half2* dst = (__half2*)(g_zh + (size_t)row * D);
    dst[lane * 2 + 0]  = __floats2half2_rn(v0.x * sc, v0.y * sc);
    dst[lane * 2 + 1]  = __floats2half2_rn(v0.z * sc, v0.w * sc);
    dst[64 + lane * 2] = __floats2half2_rn(v1.x * sc, v1.y * sc);
    dst[65 + lane * 2] = __floats2half2_rn(v1.z * sc, v1.w * sc);
}

// ---------------------------------------------------------------------------
// Stage loader: A(128x32) + B(128x32) fp16 tiles via cp.async.
// ---------------------------------------------------------------------------
__device__ __forceinline__ void load_stage(uint32_t sbase, int rb, int cb,
                                           int k0, int tid) {
    const uint32_t aB = sbase, bB = sbase + BM * PITCH;
#pragma unroll
    for (int i = 0; i < 2; i++) {
        int t = tid + i * 256;
        int row = t >> 2, seg = t & 3;
        uint32_t so = (uint32_t)(row * PITCH + seg * 16);
        cp_async16(aB + so, g_zh + (size_t)(rb + row) * D + k0 + seg * 8);
        cp_async16(bB + so, g_zh + (size_t)(cb + row) * D + k0 + seg * 8);
    }
}

// ---------------------------------------------------------------------------
// Kernel 2: fp16 HMMA sim-GEMM on UPPER-TRIANGULAR tiles only (symmetry).
// Off-diagonal tile (it<jt): exp values feed denom of both rows AND cols.
// ---------------------------------------------------------------------------
__global__ __launch_bounds__(256, 2) void kmain_hmma() {
    extern __shared__ char smem[];
    const uint32_t sb = smem_u32(smem);
    float* red_row = (float*)(smem + REDR_OFF);   // [128][4]
    float* red_col = (float*)(smem + REDC_OFF);   // [128][2]

    // Triangular decode: linear blockIdx -> (it, jt), it <= jt.
    int rem = blockIdx.x;
    int it = 0;
    while (rem >= NRT - it) { rem -= NRT - it; it++; }
    const int jt = it + rem;
    const bool offd = (jt > it);
    const bool haspos = (jt == it + NB / BM);   // only these tiles hold gm+NB

    const int tid = threadIdx.x;
    const int wid = tid >> 5, lid = tid & 31;
    const int wm = wid >> 2;                  // 0..1  (rows wm*64)
    const int wn = wid & 3;                   // 0..3  (cols wn*32)
    const int rb = it * BM;
    const int cb = jt * BN;

    float acc[4][4][4];
#pragma unroll
    for (int i = 0; i < 4; i++)
#pragma unroll
        for (int j = 0; j < 4; j++)
#pragma unroll
            for (int e = 0; e < 4; e++) acc[i][j][e] = 0.0f;

    // Prologue: fill 3 of 4 stages
    load_stage(sb + 0 * STAGE_BYTES, rb, cb, 0 * BK, tid); CP_COMMIT();
    load_stage(sb + 1 * STAGE_BYTES, rb, cb, 1 * BK, tid); CP_COMMIT();
    load_stage(sb + 2 * STAGE_BYTES, rb, cb, 2 * BK, tid); CP_COMMIT();

    const int arow  = (lid & 7) + ((lid >> 3) & 1) * 8;
    const int akoff = (lid >> 4) * 16;
    // B ldsm4 addressing: matrices m = lid>>3 -> j-sub = m>>1, k-half = m&1
    const int bjrow = ((lid >> 4) & 1) * 8 + (lid & 7);
    const int bkoff = ((lid >> 3) & 1) * 16;

#pragma unroll
    for (int k = 0; k < NKC; k++) {
        if (k <= 5)      { CP_WAIT(2); }
        else if (k == 6) { CP_WAIT(1); }
        else             { CP_WAIT(0); }
        __syncthreads();
        if (k + 3 < NKC) {
            load_stage(sb + ((k + 3) & 3) * STAGE_BYTES, rb, cb, (k + 3) * BK, tid);
            CP_COMMIT();
        }
        const uint32_t aB = sb + (k & 3) * STAGE_BYTES;
        const uint32_t bB = aB + BM * PITCH;
#pragma unroll
        for (int kf = 0; kf < 2; kf++) {
            uint32_t af[4][4], bf[4][2];
#pragma unroll
            for (int i = 0; i < 4; i++)
                ldsm4(af[i], aB + (uint32_t)((wm * 64 + i * 16 + arow) * PITCH
                                             + kf * 32 + akoff));
#pragma unroll
            for (int q = 0; q < 2; q++) {
                uint32_t br[4];
                ldsm4(br, bB + (uint32_t)((wn * 32 + q * 16 + bjrow) * PITCH
                                          + kf * 32 + bkoff));
                bf[q * 2 + 0][0] = br[0]; bf[q * 2 + 0][1] = br[1];
                bf[q * 2 + 1][0] = br[2]; bf[q * 2 + 1][1] = br[3];
            }
#pragma unroll
            for (int i = 0; i < 4; i++)
#pragma unroll
                for (int j = 0; j < 4; j++)
                    mma16816(acc[i][j], af[i], bf[j]);
        }
    }

    // Fragment coords: row = wm*64 + i*16 + (lid>>2) + (e>=2)*8
    //                  col = wn*32 + j*8  + (lid&3)*2 + (e&1)
    const int r0 = lid >> 2;
    const int c0 = (lid & 3) * 2;

    // Pass 0: exp in place (+ pos capture, + self-diagonal mask on diag tiles)
#pragma unroll
    for (int i = 0; i < 4; i++)
#pragma unroll
        for (int j = 0; j < 4; j++)
#pragma unroll
            for (int e = 0; e < 4; e++) {
                const float v = acc[i][j][e];
                float ev = __expf(v * 2.0f);
                if (haspos) {
                    const int lm = wm * 64 + i * 16 + r0 + (e >> 1) * 8;
                    const int ln = wn * 32 + j * 8 + c0 + (e & 1);
                    if (ln == lm) { g_pos[rb + lm] = v; g_pos[cb + ln] = v; }
                }
                if (!offd) {
                    const int lm = wm * 64 + i * 16 + r0 + (e >> 1) * 8;
                    const int ln = wn * 32 + j * 8 + c0 + (e & 1);
                    if (ln == lm) ev = 0.0f;     // exclude self-similarity
                }
                acc[i][j][e] = ev;
            }

    // Pass 1: row sums -> red_row
    {
        float rsum[4][2];
#pragma unroll
        for (int i = 0; i < 4; i++) { rsum[i][0] = 0.0f; rsum[i][1] = 0.0f; }
#pragma unroll
        for (int i = 0; i < 4; i++)
#pragma unroll
            for (int j = 0; j < 4; j++) {
                rsum[i][0] += acc[i][j][0] + acc[i][j][1];
                rsum[i][1] += acc[i][j][2] + acc[i][j][3];
            }
#pragma unroll
        for (int i = 0; i < 4; i++)
#pragma unroll
            for (int h = 0; h < 2; h++) {
#pragma unroll
                for (int off = 1; off <= 2; off <<= 1)
                    rsum[i][h] += __shfl_xor_sync(0xffffffffu, rsum[i][h], off);
            }
        if ((lid & 3) == 0) {
#pragma unroll
            for (int i = 0; i < 4; i++)
#pragma unroll
                for (int h = 0; h < 2; h++)
                    red_row[(wm * 64 + i * 16 + r0 + h * 8) * 4 + wn] = rsum[i][h];
        }
    }

    // Pass 2 (off-diag only): col sums -> red_col
    if (offd) {
        float csum[4][2];
#pragma unroll
        for (int j = 0; j < 4; j++) { csum[j][0] = 0.0f; csum[j][1] = 0.0f; }
#pragma unroll
        for (int i = 0; i < 4; i++)
#pragma unroll
            for (int j = 0; j < 4; j++) {
                csum[j][0] += acc[i][j][0] + acc[i][j][2];
                csum[j][1] += acc[i][j][1] + acc[i][j][3];
            }
#pragma unroll
        for (int j = 0; j < 4; j++)
#pragma unroll
            for (int ec = 0; ec < 2; ec++) {
#pragma unroll
                for (int off = 4; off <= 16; off <<= 1)
                    csum[j][ec] += __shfl_xor_sync(0xffffffffu, csum[j][ec], off);
            }
        if (lid < 4) {
#pragma unroll
            for (int j = 0; j < 4; j++)
#pragma unroll
                for (int ec = 0; ec < 2; ec++)
                    red_col[(wn * 32 + j * 8 + lid * 2 + ec) * 2 + wm] = csum[j][ec];
        }
    }
    __syncthreads();
    if (tid < BM) {
        g_partial[(size_t)(rb + tid) * NCT + jt] =
            red_row[tid * 4] + red_row[tid * 4 + 1]
          + red_row[tid * 4 + 2] + red_row[tid * 4 + 3];
        if (offd)
            g_partial[(size_t)(cb + tid) * NCT + it] =
                red_col[tid * 2] + red_col[tid * 2 + 1];
    }
}

// ---------------------------------------------------------------------------
// Kernel 3: coalesced per-row loss; last block combines deterministically.
// 64 blocks x 256 threads; block b covers rows [b*128, b*128+128).
// ---------------------------------------------------------------------------
__global__ __launch_bounds__(256) void kfinal(float* __restrict__ out) {
    __shared__ float red[8];
    __shared__ int last;
    const int warp = threadIdx.x >> 5;
    const int lane = threadIdx.x & 31;
    float acc = 0.0f;
#pragma unroll
    for (int rr = 0; rr < 16; rr++) {
        const int row = blockIdx.x * 128 + warp * 16 + rr;
        const float* p = g_partial + (size_t)row * NCT;
        float s = p[lane] + p[lane + 32];
#pragma unroll
        for (int off = 16; off > 0; off >>= 1)
            s += __shfl_xor_sync(0xffffffffu, s, off);
        if (lane == 0) acc += -g_pos[row] * 2.0f + logf(s);
    }
    if (lane == 0) red[warp] = acc;
    __syncthreads();
    if (threadIdx.x == 0) {
        float t = 0.0f;
#pragma unroll
        for (int w = 0; w < 8; w++) t += red[w];
        g_blocksum[blockIdx.x] = t;
        __threadfence();
        last = (atomicAdd(&g_ctr, 1) == FBLK - 1);
    }
    __syncthreads();
    if (last && threadIdx.x == 0) {
        float t = 0.0f;
#pragma unroll
        for (int b = 0; b < FBLK; b++) t += g_blocksum[b];  // fixed order
        out[0] = t / (float)N2;
    }
}

// ---------------------------------------------------------------------------
extern "C" void kernel_launch(void* const* d_in, const int* in_sizes, int n_in,
                              void* d_out, int out_size) {
    const float* xi = (const float*)d_in[0];
    const float* xj = (const float*)d_in[1];
    float* out = (float*)d_out;
    (void)in_sizes; (void)n_in; (void)out_size;

    cudaFuncSetAttribute(kmain_hmma,
                         cudaFuncAttributeMaxDynamicSharedMemorySize, SMEM_BYTES);

    knorm<<<N2 / 8, 256>>>(xi, xj);
    kmain_hmma<<<NTRI, 256, SMEM_BYTES>>>();
    kfinal<<<FBLK, 256>>>(out);
}

// round 9
// speedup vs baseline: 1.1197x; 1.0410x over previous
#include <cuda_runtime.h>
#include <cuda_fp16.h>
#include <math.h>
#include <stdint.h>

// Problem constants (fixed shapes: B=4096, D=256, T=0.5)
#define NB     4096
#define D      256
#define N2     8192
#define BM     128
#define BN     256
#define BK     32
#define NKC    (D / BK)      // 8 k-chunks
#define NJT    (N2 / BN)     // 32 col tiles
#define NTILE  (NJT * (NJT + 1))       // 1056 tiles: (it,jt), it <= 2jt+1
#define NCTW   96            // partial slots per row: [0,32)=row jt, [32,96)=col it
#define PITCH  80            // smem row pitch bytes (64B data + 16B pad)
#define STAGE_BYTES ((BM + BN) * PITCH)  // 30720
#define NSTAGE 3
#define REDR_OFF (NSTAGE * STAGE_BYTES)           // 92160: red_row[128][4]
#define REDC_OFF (REDR_OFF + BM * 4 * 4)          // red_col[256][2]
#define SMEM_BYTES (REDC_OFF + BN * 2 * 4 + 256)
#define FBLK   64            // kfinal blocks (128 rows each)

// Scratch (static device globals; no allocation allowed)
__device__ __half g_zh[N2 * D];         // normalized rows, fp16
__device__ float g_partial[N2 * NCTW];  // per-row exp-sum partials (unused slots stay 0)
__device__ float g_pos[N2];             // sim[k, k +- NB]
__device__ float g_blocksum[FBLK];      // per-block loss partial
__device__ int   g_ctr;                 // kfinal completion counter

// ---------------------------------------------------------------------------
__device__ __forceinline__ uint32_t smem_u32(const void* p) {
    uint32_t a;
    asm("{ .reg .u64 t; cvta.to.shared.u64 t, %1; cvt.u32.u64 %0, t; }"
        : "=r"(a) : "l"(p));
    return a;
}
__device__ __forceinline__ void cp_async16(uint32_t smem, const void* g) {
    asm volatile("cp.async.cg.shared.global [%0], [%1], 16;" :: "r"(smem), "l"(g));
}
#define CP_COMMIT() asm volatile("cp.async.commit_group;" ::: "memory")
#define CP_WAIT(n)  asm volatile("cp.async.wait_group %0;" :: "n"(n) : "memory")

__device__ __forceinline__ void ldsm4(uint32_t* r, uint32_t addr) {
    asm volatile("ldmatrix.sync.aligned.m8n8.x4.shared.b16 {%0,%1,%2,%3}, [%4];"
        : "=r"(r[0]), "=r"(r[1]), "=r"(r[2]), "=r"(r[3]) : "r"(addr));
}
// f16-accumulator HMMA
__device__ __forceinline__ void mma16816h(uint32_t* c, const uint32_t* a,
                                          const uint32_t* b) {
    asm volatile("mma.sync.aligned.m16n8k16.row.col.f16.f16.f16.f16 "
        "{%0,%1}, {%2,%3,%4,%5}, {%6,%7}, {%0,%1};"
        : "+r"(c[0]), "+r"(c[1])
        : "r"(a[0]), "r"(a[1]), "r"(a[2]), "r"(a[3]), "r"(b[0]), "r"(b[1]));
}

// ---------------------------------------------------------------------------
// Kernel 1: L2-normalize rows of x_i / x_j (fp32 math) into fp16 g_zh.
// ---------------------------------------------------------------------------
__global__ __launch_bounds__(256) void knorm(const float* __restrict__ xi,
                                             const float* __restrict__ xj) {
    if (blockIdx.x == 0 && threadIdx.x == 0) g_ctr = 0;   // reset kfinal counter
    int warp = threadIdx.x >> 5;
    int lane = threadIdx.x & 31;
    int row  = blockIdx.x * 8 + warp;
    const float* src = (row < NB) ? (xi + (size_t)row * D)
                                  : (xj + (size_t)(row - NB) * D);
    float4 v0 = ((const float4*)src)[lane];
    float4 v1 = ((const float4*)src)[lane + 32];
    float ss = v0.x*v0.x + v0.y*v0.y + v0.z*v0.z + v0.w*v0.w
             + v1.x*v1.x + v1.y*v1.y + v1.z*v1.z + v1.w*v1.w;
#pragma unroll
    for (int off = 16; off > 0; off >>= 1)
        ss += __shfl_xor_sync(0xffffffffu, ss, off);
    float sc = 1.0f / fmaxf(sqrtf(ss), 1e-12f);
    __half2* dst = (__half2*)(g_zh + (size_t)row * D);
    dst[lane * 2 + 0]  = __floats2half2_rn(v0.x * sc, v0.y * sc);
    dst[lane * 2 + 1]  = __floats2half2_rn(v0.z * sc, v0.w * sc);
    dst[64 + lane * 2] = __floats2half2_rn(v1.x * sc, v1.y * sc);
    dst[65 + lane * 2] = __floats2half2_rn(v1.z * sc, v1.w * sc);
}

// ---------------------------------------------------------------------------
// Stage loader: A(128x32) + B(256x32) fp16 tiles via cp.async.
// A rows at [0,128), B rows at [128,384) -- contiguous pitch layout.
// ---------------------------------------------------------------------------
__device__ __forceinline__ void load_stage(uint32_t sbase, int rb, int cb,
                                           int k0, int tid) {
#pragma unroll
    for (int i = 0; i < 6; i++) {          // 1536 16B segments / 256 threads
        int t = tid + i * 256;
        int row = t >> 2, seg = t & 3;
        int grow = (row < BM) ? (rb + row) : (cb + row - BM);
        cp_async16(sbase + (uint32_t)(row * PITCH + seg * 16),
                   g_zh + (size_t)grow * D + k0 + seg * 8);
    }
}

// ---------------------------------------------------------------------------
// Kernel 2: fp16 HMMA sim-GEMM, 128x256 CTA tile, warp tile 64x64, f16 acc.
// Tiles (it, jt) with it <= 2jt+1 cover each unordered 128-block pair once.
// Col-half rules: block < it -> excluded (dup); == it -> diag (rsum only,
// self masked); > it -> full (rsum + csum).
// ---------------------------------------------------------------------------
__global__ __launch_bounds__(256, 2) void kmain_hmma() {
    extern __shared__ char smem[];
    const uint32_t sb = smem_u32(smem);
    float* red_row = (float*)(smem + REDR_OFF);   // [128][4]
    float* red_col = (float*)(smem + REDC_OFF);   // [256][2]

    // Decode blockIdx -> (jt, it): base(jt) = jt*(jt+1), count 2jt+2.
    const int x = blockIdx.x;
    int jt = (int)((sqrtf(4.0f * x + 1.0f) - 1.0f) * 0.5f);
    while ((jt + 1) * (jt + 2) <= x) jt++;
    while (jt * (jt + 1) > x) jt--;
    const int it = x - jt * (jt + 1);            // 0 .. 2jt+1

    const bool haspos = (jt == (it >> 1) + 16);
    const int  poff   = (it & 1) * 128;
    const int rb = it * BM;
    const int cb = jt * BN;

    const int tid = threadIdx.x;
    const int wid = tid >> 5, lid = tid & 31;
    const int wm = wid >> 2;                  // 0..1  (rows wm*64)
    const int wn = wid & 3;                   // 0..3  (cols wn*64)

    uint32_t acc[4][8][2];
#pragma unroll
    for (int i = 0; i < 4; i++)
#pragma unroll
        for (int j = 0; j < 8; j++) { acc[i][j][0] = 0u; acc[i][j][1] = 0u; }

    // Prologue: 2 of 3 stages in flight
    load_stage(sb + 0 * STAGE_BYTES, rb, cb, 0 * BK, tid); CP_COMMIT();
    load_stage(sb + 1 * STAGE_BYTES, rb, cb, 1 * BK, tid); CP_COMMIT();

    const int arow  = (lid & 7) + ((lid >> 3) & 1) * 8;
    const int akoff = (lid >> 4) * 16;
    const int bjrow = ((lid >> 4) & 1) * 8 + (lid & 7);
    const int bkoff = ((lid >> 3) & 1) * 16;

#pragma unroll
    for (int k = 0; k < NKC; k++) {
        if (k < NKC - 1) { CP_WAIT(1); } else { CP_WAIT(0); }
        __syncthreads();
        if (k + 2 < NKC) {
            load_stage(sb + ((k + 2) % 3) * STAGE_BYTES, rb, cb, (k + 2) * BK, tid);
            CP_COMMIT();
        }
        const uint32_t aB = sb + (k % 3) * STAGE_BYTES;
        const uint32_t bB = aB + BM * PITCH;
#pragma unroll
        for (int kf = 0; kf < 2; kf++) {
            uint32_t af[4][4], bf[8][2];
#pragma unroll
            for (int i = 0; i < 4; i++)
                ldsm4(af[i], aB + (uint32_t)((wm * 64 + i * 16 + arow) * PITCH
                                             + kf * 32 + akoff));
#pragma unroll
            for (int q = 0; q < 4; q++) {
                uint32_t br[4];
                ldsm4(br, bB + (uint32_t)((wn * 64 + q * 16 + bjrow) * PITCH
                                          + kf * 32 + bkoff));
                bf[q * 2 + 0][0] = br[0]; bf[q * 2 + 0][1] = br[1];
                bf[q * 2 + 1][0] = br[2]; bf[q * 2 + 1][1] = br[3];
            }
#pragma unroll
            for (int i = 0; i < 4; i++)
#pragma unroll
                for (int j = 0; j < 8; j++)
                    mma16816h(acc[i][j], af[i], bf[j]);
        }
    }

    // Fragment coords: row = wm*64 + i*16 + (lid>>2) + e*8
    //                  cols = wn*64 + j*8 + (lid&3)*2 + {0,1}
    const int r0 = lid >> 2;
    const int c0 = (lid & 3) * 2;

    float rsum[4][2];
    float csum[8][2];
#pragma unroll
    for (int i = 0; i < 4; i++) { rsum[i][0] = 0.0f; rsum[i][1] = 0.0f; }
#pragma unroll
    for (int j = 0; j < 8; j++) { csum[j][0] = 0.0f; csum[j][1] = 0.0f; }

#pragma unroll
    for (int j = 0; j < 8; j++) {
        const int jcol  = wn * 64 + j * 8;           // uniform 128-half per frag
        const int half  = jcol >> 7;
        const int cbblk = 2 * jt + half;
        const bool excl   = (cbblk < it);
        const bool diag   = (cbblk == it);
        const bool cvalid = (cbblk > it);
#pragma unroll
        for (int i = 0; i < 4; i++)
#pragma unroll
            for (int e = 0; e < 2; e++) {
                const __half2 h2 = *(__half2*)&acc[i][j][e];
                const float2 v2 = __half22float2(h2);
                const int lm  = wm * 64 + i * 16 + r0 + e * 8;
                const int ln0 = jcol + c0;
                if (haspos) {
                    if (ln0 == lm + poff) {
                        g_pos[rb + lm] = v2.x; g_pos[cb + ln0] = v2.x;
                    }
                    if (ln0 + 1 == lm + poff) {
                        g_pos[rb + lm] = v2.y; g_pos[cb + ln0 + 1] = v2.y;
                    }
                }
                float ev0 = __expf(v2.x * 2.0f);
                float ev1 = __expf(v2.y * 2.0f);
                if (excl) { ev0 = 0.0f; ev1 = 0.0f; }
                if (diag) {
                    if (ln0 - 128 * half == lm)     ev0 = 0.0f;
                    if (ln0 + 1 - 128 * half == lm) ev1 = 0.0f;
                }
                rsum[i][e] += ev0 + ev1;
                if (cvalid) { csum[j][0] += ev0; csum[j][1] += ev1; }
            }
    }

    // Row reduce: over lanes sharing a row (lid&3 -> xor 1,2), then 4 n-warps.
#pragma unroll
    for (int i = 0; i < 4; i++)
#pragma unroll
        for (int e = 0; e < 2; e++) {
#pragma unroll
            for (int off = 1; off <= 2; off <<= 1)
                rsum[i][e] += __shfl_xor_sync(0xffffffffu, rsum[i][e], off);
        }
    if ((lid & 3) == 0) {
#pragma unroll
        for (int i = 0; i < 4; i++)
#pragma unroll
            for (int e = 0; e < 2; e++)
                red_row[(wm * 64 + i * 16 + r0 + e * 8) * 4 + wn] = rsum[i][e];
    }

    // Col reduce: over the 8 lane row-groups (xor 4,8,16), then 2 m-warps.
#pragma unroll
    for (int j = 0; j < 8; j++)
#pragma unroll
        for (int cp = 0; cp < 2; cp++) {
#pragma unroll
            for (int off = 4; off <= 16; off <<= 1)
                csum[j][cp] += __shfl_xor_sync(0xffffffffu, csum[j][cp], off);
        }
    if (lid < 4) {
#pragma unroll
        for (int j = 0; j < 8; j++)
#pragma unroll
            for (int cp = 0; cp < 2; cp++)
                red_col[(wn * 64 + j * 8 + lid * 2 + cp) * 2 + wm] = csum[j][cp];
    }
    __syncthreads();
    if (tid < BM) {
        g_partial[(size_t)(rb + tid) * NCTW + jt] =
            red_row[tid * 4] + red_row[tid * 4 + 1]
          + red_row[tid * 4 + 2] + red_row[tid * 4 + 3];
    }
    // col partials: every thread handles one of the 256 columns
    g_partial[(size_t)(cb + tid) * NCTW + 32 + it] =
        red_col[tid * 2] + red_col[tid * 2 + 1];
}

// ---------------------------------------------------------------------------
// Kernel 3: coalesced per-row loss; last block combines deterministically.
// ---------------------------------------------------------------------------
__global__ __launch_bounds__(256) void kfinal(float* __restrict__ out) {
    __shared__ float red[8];
    __shared__ int last;
    const int warp = threadIdx.x >> 5;
    const int lane = threadIdx.x & 31;
    float acc = 0.0f;
#pragma unroll
    for (int rr = 0; rr < 16; rr++) {
        const int row = blockIdx.x * 128 + warp * 16 + rr;
        const float* p = g_partial + (size_t)row * NCTW;
        float s = p[lane] + p[lane + 32] + p[lane + 64];
#pragma unroll
        for (int off = 16; off > 0; off >>= 1)
            s += __shfl_xor_sync(0xffffffffu, s, off);
        if (lane == 0) acc += -g_pos[row] * 2.0f + logf(s);
    }
    if (lane == 0) red[warp] = acc;
    __syncthreads();
    if (threadIdx.x == 0) {
        float t = 0.0f;
#pragma unroll
        for (int w = 0; w < 8; w++) t += red[w];
        g_blocksum[blockIdx.x] = t;
        __threadfence();
        last = (atomicAdd(&g_ctr, 1) == FBLK - 1);
    }
    __syncthreads();
    if (last && threadIdx.x == 0) {
        float t = 0.0f;
#pragma unroll
        for (int b = 0; b < FBLK; b++) t += g_blocksum[b];  // fixed order
        out[0] = t / (float)N2;
    }
}

// ---------------------------------------------------------------------------
extern "C" void kernel_launch(void* const* d_in, const int* in_sizes, int n_in,
                              void* d_out, int out_size) {
    const float* xi = (const float*)d_in[0];
    const float* xj = (const float*)d_in[1];
    float* out = (float*)d_out;
    (void)in_sizes; (void)n_in; (void)out_size;

    cudaFuncSetAttribute(kmain_hmma,
                         cudaFuncAttributeMaxDynamicSharedMemorySize, SMEM_BYTES);

    knorm<<<N2 / 8, 256>>>(xi, xj);
    kmain_hmma<<<NTILE, 256, SMEM_BYTES>>>();
    kfinal<<<FBLK, 256>>>(out);
}